// round 14
// baseline (speedup 1.0000x reference)
#include <cuda_runtime.h>
#include <cuda_fp16.h>
#include <cstdint>

// ---------------------------------------------------------------------------
// BinaryTreeComposer on sm_103 (plain target — no tcgen05).
// R14: R13 champion + vectorized (float4) gate epilogue + finer cp.async
// interleave (4 bursts/kstep). Mainloop structure unchanged (smem-crossbar
// co-saturated optimum).
// ---------------------------------------------------------------------------

#define BATCH 4096
#define DDIM  2048
#define KTOT  4096
#define NTOT  8192

__device__ __align__(128) __half g_Ah[(size_t)BATCH * KTOT];   // 32 MB, [M][K]
__device__ __align__(128) __half g_Wh[(size_t)NTOT * KTOT];    // 64 MB, [N][K]

// ---------------------------------------------------------------------------
// helpers
// ---------------------------------------------------------------------------
__device__ __forceinline__ uint32_t smem_u32(const void* p) {
    uint32_t a;
    asm("{ .reg .u64 t; cvta.to.shared.u64 t, %1; cvt.u32.u64 %0, t; }" : "=r"(a) : "l"(p));
    return a;
}
__device__ __forceinline__ void cp_async16(uint32_t dst, const void* src) {
    asm volatile("cp.async.cg.shared.global [%0], [%1], 16;" :: "r"(dst), "l"(src) : "memory");
}
#define CP_COMMIT() asm volatile("cp.async.commit_group;" ::: "memory")
#define CP_WAIT(n)  asm volatile("cp.async.wait_group %0;" :: "n"(n) : "memory")

#define LDSM4(r0, r1, r2, r3, addr)                                            \
    asm volatile("ldmatrix.sync.aligned.m8n8.x4.shared.b16 {%0,%1,%2,%3}, [%4];" \
                 : "=r"(r0), "=r"(r1), "=r"(r2), "=r"(r3) : "r"(addr))

#define MMA_F16(d, a, b)                                                       \
    asm volatile("mma.sync.aligned.m16n8k16.row.col.f32.f16.f16.f32 "          \
                 "{%0,%1,%2,%3}, {%4,%5,%6,%7}, {%8,%9}, {%0,%1,%2,%3};"       \
                 : "+f"((d)[0]), "+f"((d)[1]), "+f"((d)[2]), "+f"((d)[3])       \
                 : "r"((a)[0]), "r"((a)[1]), "r"((a)[2]), "r"((a)[3]),          \
                   "r"((b)[0]), "r"((b)[1]))

__device__ __forceinline__ uint32_t h2bits(__half2 h) {
    return *reinterpret_cast<uint32_t*>(&h);
}

// ---------------------------------------------------------------------------
// merged prep kernel (unchanged from R13)
// ---------------------------------------------------------------------------
#define PREP_A_BLOCKS 8192
#define PREP_W_BLOCKS 8192

__global__ void prep_all(const float* __restrict__ lh, const float* __restrict__ rh,
                         const float* __restrict__ Wl, const float* __restrict__ Wr) {
    __shared__ float s[64][65];
    const int t = threadIdx.x;

    if (blockIdx.x < PREP_A_BLOCKS) {
        size_t idx = (size_t)blockIdx.x * 256 + t;
        size_t m = idx >> 9;
        int q = (int)(idx & 511);
        const float* src = (q < 256) ? (lh + (size_t)m * DDIM + q * 8)
                                     : (rh + (size_t)m * DDIM + (q - 256) * 8);
        float4 v0 = *reinterpret_cast<const float4*>(src);
        float4 v1 = *reinterpret_cast<const float4*>(src + 4);
        uint4 w;
        w.x = h2bits(__floats2half2_rn(v0.x, v0.y));
        w.y = h2bits(__floats2half2_rn(v0.z, v0.w));
        w.z = h2bits(__floats2half2_rn(v1.x, v1.y));
        w.w = h2bits(__floats2half2_rn(v1.z, v1.w));
        *reinterpret_cast<uint4*>(g_Ah + m * KTOT + ((size_t)q << 3)) = w;
        return;
    }

    const int bid = blockIdx.x - PREP_A_BLOCKS;
    const int kb = (bid & 63) * 64;
    const int nb = (bid >> 6) * 64;

    const int rr = t >> 4;
    const int c4 = (t & 15) * 4;
#pragma unroll
    for (int i = 0; i < 4; ++i) {
        int k = kb + rr + i * 16;
        const float* src = (k < DDIM) ? (Wl + (size_t)k * NTOT)
                                      : (Wr + (size_t)(k - DDIM) * NTOT);
        float4 v = *reinterpret_cast<const float4*>(src + nb + c4);
        s[rr + i * 16][c4 + 0] = v.x;
        s[rr + i * 16][c4 + 1] = v.y;
        s[rr + i * 16][c4 + 2] = v.z;
        s[rr + i * 16][c4 + 3] = v.w;
    }
    __syncthreads();

    const int koff = (t & 7) * 8;
#pragma unroll
    for (int i = 0; i < 2; ++i) {
        int nrow = (t >> 3) + i * 32;
        uint4 w;
        w.x = h2bits(__floats2half2_rn(s[koff + 0][nrow], s[koff + 1][nrow]));
        w.y = h2bits(__floats2half2_rn(s[koff + 2][nrow], s[koff + 3][nrow]));
        w.z = h2bits(__floats2half2_rn(s[koff + 4][nrow], s[koff + 5][nrow]));
        w.w = h2bits(__floats2half2_rn(s[koff + 6][nrow], s[koff + 7][nrow]));
        *reinterpret_cast<uint4*>(g_Wh + (size_t)(nb + nrow) * KTOT + kb + koff) = w;
    }
}

// ---------------------------------------------------------------------------
// Fused GEMM + gates. CTA 128m x 128n (4 gate quarters x 32 cols of D),
// BK=64 f16 (128B rows), 256 thr (8 warps 2x4, warp tile 64x32), STG=3,
// 2 CTA/SM.
// ---------------------------------------------------------------------------
#define BM 128
#define BN 128
#define BK 64
#define STG 3
#define KSTEPS (KTOT / BK)                 // 64
#define A_BYTES (BM * BK * 2)              // 16384
#define B_BYTES (BN * BK * 2)              // 16384
#define STAGE_BYTES (A_BYTES + B_BYTES)    // 32768
#define SMEM_BYTES (STG * STAGE_BYTES)     // 98304 (>= 128*132*4 epilogue)

// half-stage loads: 2 cp.async per thread each
__device__ __forceinline__ void load_A_half(uint32_t as, int tid,
                                            const __half* aSrc, int h) {
#pragma unroll
    for (int i = 0; i < 2; ++i) {
        int id = tid + (i << 8) + (h << 9);
        int row = id >> 3, c = id & 7;
        uint32_t dst = as + row * 128 + ((c ^ (row & 7)) << 4);
        cp_async16(dst, aSrc + (size_t)row * KTOT + (c << 3));
    }
}
__device__ __forceinline__ void load_B_half(uint32_t bs, int tid,
                                            const __half* bSrc, int h) {
#pragma unroll
    for (int i = 0; i < 2; ++i) {
        int id = tid + (i << 8) + (h << 9);
        int row = id >> 3, c = id & 7;
        int wrow = row + ((row >> 5) * (DDIM - 32));   // quarter gather
        uint32_t dst = bs + row * 128 + ((c ^ (row & 7)) << 4);
        cp_async16(dst, bSrc + (size_t)wrow * KTOT + (c << 3));
    }
}

// one kq group (k16): B then A fragments, then 16 MMAs (warp 64x32)
__device__ __forceinline__ void kq_group(int kq, uint32_t aWarp, uint32_t bWarp,
                                         uint32_t aco, uint32_t bco, uint32_t rr,
                                         float (&ac)[4][4][4]) {
    uint32_t b[4][2];
    uint32_t bxor = ((2 * kq + bco) ^ rr) << 4;
#pragma unroll
    for (int pi = 0; pi < 2; ++pi) {
        uint32_t r0, r1, r2, r3;
        LDSM4(r0, r1, r2, r3, bWarp + pi * 2048 + bxor);
        b[2 * pi][0] = r0; b[2 * pi][1] = r1;
        b[2 * pi + 1][0] = r2; b[2 * pi + 1][1] = r3;
    }
    uint32_t a[4][4];
    uint32_t axor = ((2 * kq + aco) ^ rr) << 4;
#pragma unroll
    for (int mi = 0; mi < 4; ++mi)
        LDSM4(a[mi][0], a[mi][1], a[mi][2], a[mi][3], aWarp + mi * 2048 + axor);
#pragma unroll
    for (int mi = 0; mi < 4; ++mi)
#pragma unroll
        for (int ni = 0; ni < 4; ++ni)
            MMA_F16(ac[mi][ni], a[mi], b[ni]);
}

__device__ __forceinline__ float sigm(float x) { return 1.0f / (1.0f + __expf(-x)); }
__device__ __forceinline__ float tanh_fast(float x) {
    return 1.0f - __fdividef(2.0f, __expf(2.0f * x) + 1.0f);
}

__global__ void __launch_bounds__(256, 2)
gemm_gates_kernel(const float* __restrict__ lc, const float* __restrict__ rc,
                  const float* __restrict__ bl, const float* __restrict__ br,
                  float* __restrict__ out) {
    extern __shared__ float smem[];
    uint32_t sbase = smem_u32(smem);
    const int tid = threadIdx.x;
    const int lane = tid & 31;
    const int wid = tid >> 5;
    const int wm = wid & 1;          // 0..1: 64-row m slice
    const int wn = wid >> 1;         // 0..3: 32-col n slice
    const int kq0 = wid & 3, kq1 = (wid + 1) & 3, kq2 = (wid + 2) & 3,
              kq3 = (wid + 3) & 3;

    const int nb = blockIdx.x * 32;
    const int m0 = blockIdx.y * BM;

    const __half* Abase = g_Ah + (size_t)m0 * KTOT;
    const __half* WtBase = g_Wh + (size_t)nb * KTOT;

    const uint32_t j = lane >> 3, rr = lane & 7;
    const uint32_t a_row_off = ((j & 1) << 3) + rr;  const uint32_t aco = j >> 1;
    const uint32_t b_row_off = ((j >> 1) << 3) + rr; const uint32_t bco = j & 1;

    uint32_t aW[STG], bW[STG];
#pragma unroll
    for (int s = 0; s < STG; ++s) {
        aW[s] = sbase + s * STAGE_BYTES + (wm * 64 + a_row_off) * 128;
        bW[s] = sbase + s * STAGE_BYTES + A_BYTES + (wn * 32 + b_row_off) * 128;
    }

    float ac[4][4][4];
#pragma unroll
    for (int mi = 0; mi < 4; ++mi)
#pragma unroll
        for (int ni = 0; ni < 4; ++ni)
#pragma unroll
            for (int q = 0; q < 4; ++q) ac[mi][ni][q] = 0.0f;

#pragma unroll
    for (int s = 0; s < STG - 1; ++s) {
        uint32_t as = sbase + s * STAGE_BYTES;
        load_A_half(as, tid, Abase + s * BK, 0);
        load_A_half(as, tid, Abase + s * BK, 1);
        load_B_half(as + A_BYTES, tid, WtBase + s * BK, 0);
        load_B_half(as + A_BYTES, tid, WtBase + s * BK, 1);
        CP_COMMIT();
    }

    int buf = 0;
#pragma unroll 1
    for (int ks = 0; ks < KSTEPS; ++ks) {
        CP_WAIT(1);
        __syncthreads();
        const int nxt = ks + STG - 1;
        int nbuf = buf + (STG - 1); if (nbuf >= STG) nbuf -= STG;
        const uint32_t nas = sbase + nbuf * STAGE_BYTES;
        const __half* aSrcN = Abase + nxt * BK;
        const __half* bSrcN = WtBase + nxt * BK;
        const bool doLoad = (nxt < KSTEPS);

        // rotated kq order per warp; cp.async in 4 fine bursts
        kq_group(kq0, aW[buf], bW[buf], aco, bco, rr, ac);
        if (doLoad) load_A_half(nas, tid, aSrcN, 0);
        kq_group(kq1, aW[buf], bW[buf], aco, bco, rr, ac);
        if (doLoad) load_A_half(nas, tid, aSrcN, 1);
        kq_group(kq2, aW[buf], bW[buf], aco, bco, rr, ac);
        if (doLoad) load_B_half(nas + A_BYTES, tid, bSrcN, 0);
        kq_group(kq3, aW[buf], bW[buf], aco, bco, rr, ac);
        if (doLoad) load_B_half(nas + A_BYTES, tid, bSrcN, 1);
        CP_COMMIT();

        if (++buf == STG) buf = 0;
    }

    // ---- fused epilogue (vectorized float4) ----
    CP_WAIT(0);
    __syncthreads();
    float* sG = smem;                // [128][132] padded (132 keeps 16B align)
    const int gq = lane >> 2, t4 = lane & 3;
#pragma unroll
    for (int mi = 0; mi < 4; ++mi) {
#pragma unroll
        for (int ni = 0; ni < 4; ++ni) {
            int m = wm * 64 + mi * 16 + gq;
            int n = wn * 32 + ni * 8 + 2 * t4;
            sG[m * 132 + n]           = ac[mi][ni][0];
            sG[m * 132 + n + 1]       = ac[mi][ni][1];
            sG[(m + 8) * 132 + n]     = ac[mi][ni][2];
            sG[(m + 8) * 132 + n + 1] = ac[mi][ni][3];
        }
    }
    __syncthreads();

    // thread -> 4-column strip: cq = tid&7 (8 strips of 4 cols), rows tid>>3 + 32*it
    const int cq = tid & 7;
    const int r0base = tid >> 3;     // 0..31
    const int gn4 = nb + cq * 4;     // global column of strip start

    const float4 bi0 = *reinterpret_cast<const float4*>(bl + gn4);
    const float4 bi1 = *reinterpret_cast<const float4*>(br + gn4);
    const float4 bf0 = *reinterpret_cast<const float4*>(bl + DDIM + gn4);
    const float4 bf1 = *reinterpret_cast<const float4*>(br + DDIM + gn4);
    const float4 bg0 = *reinterpret_cast<const float4*>(bl + 2 * DDIM + gn4);
    const float4 bg1 = *reinterpret_cast<const float4*>(br + 2 * DDIM + gn4);
    const float4 bu0 = *reinterpret_cast<const float4*>(bl + 3 * DDIM + gn4);
    const float4 bu1 = *reinterpret_cast<const float4*>(br + 3 * DDIM + gn4);

#pragma unroll
    for (int it = 0; it < 4; ++it) {
        const int r = r0base + it * 32;
        const size_t mrow = (size_t)(m0 + r) * DDIM;
        float4 gi = *reinterpret_cast<const float4*>(sG + r * 132 + cq * 4);
        float4 gl = *reinterpret_cast<const float4*>(sG + r * 132 + 32 + cq * 4);
        float4 gr = *reinterpret_cast<const float4*>(sG + r * 132 + 64 + cq * 4);
        float4 gu = *reinterpret_cast<const float4*>(sG + r * 132 + 96 + cq * 4);
        float4 vlc = *reinterpret_cast<const float4*>(lc + mrow + gn4);
        float4 vrc = *reinterpret_cast<const float4*>(rc + mrow + gn4);
        float4 c, h;
#define GATE1(X, BI0, BI1, BF0, BF1, BG0, BG1, BU0, BU1)                       \
        do {                                                                   \
            float i_ = sigm(gi.X + BI0.X + BI1.X);                             \
            float lf = sigm(gl.X + BF0.X + BF1.X);                             \
            float rf = sigm(gr.X + BG0.X + BG1.X);                             \
            float u_ = tanh_fast(gu.X + BU0.X + BU1.X);                        \
            c.X = i_ * u_ + lf * vlc.X + rf * vrc.X;                           \
            h.X = tanh_fast(c.X);                                              \
        } while (0)
        GATE1(x, bi0, bi1, bf0, bf1, bg0, bg1, bu0, bu1);
        GATE1(y, bi0, bi1, bf0, bf1, bg0, bg1, bu0, bu1);
        GATE1(z, bi0, bi1, bf0, bf1, bg0, bg1, bu0, bu1);
        GATE1(w, bi0, bi1, bf0, bf1, bg0, bg1, bu0, bu1);
#undef GATE1
        *reinterpret_cast<float4*>(out + mrow + gn4) = c;
        *reinterpret_cast<float4*>(out + (size_t)BATCH * DDIM + mrow + gn4) = h;
    }
}

// ---------------------------------------------------------------------------
// launch — inputs: lc, lh, rc, rh, Wl, bl, Wr, br (all f32)
// ---------------------------------------------------------------------------
extern "C" void kernel_launch(void* const* d_in, const int* in_sizes, int n_in,
                              void* d_out, int out_size) {
    const float* lc = (const float*)d_in[0];
    const float* lh = (const float*)d_in[1];
    const float* rc = (const float*)d_in[2];
    const float* rh = (const float*)d_in[3];
    const float* Wl = (const float*)d_in[4];
    const float* bl = (const float*)d_in[5];
    const float* Wr = (const float*)d_in[6];
    const float* br = (const float*)d_in[7];
    float* out = (float*)d_out;

    prep_all<<<PREP_A_BLOCKS + PREP_W_BLOCKS, 256>>>(lh, rh, Wl, Wr);

    cudaFuncSetAttribute(gemm_gates_kernel,
                         cudaFuncAttributeMaxDynamicSharedMemorySize, SMEM_BYTES);
    gemm_gates_kernel<<<dim3(DDIM / 32, BATCH / BM), 256, SMEM_BYTES>>>(
        lc, rc, bl, br, out);
}

// round 15
// speedup vs baseline: 1.0765x; 1.0765x over previous
#include <cuda_runtime.h>
#include <cuda_fp16.h>
#include <cstdint>

// ---------------------------------------------------------------------------
// BinaryTreeComposer on sm_103 (plain target — no tcgen05).
// R15: R13 champion mainloop EXACTLY (fp16 m16n8k16, CTA 128x128, warp 64x32,
// 256 thr, 2 CTA/SM, STG=3, 2-burst cp.async interleave) + float4-vectorized
// gate epilogue (the good half of R14).
// ---------------------------------------------------------------------------

#define BATCH 4096
#define DDIM  2048
#define KTOT  4096
#define NTOT  8192

__device__ __align__(128) __half g_Ah[(size_t)BATCH * KTOT];   // 32 MB, [M][K]
__device__ __align__(128) __half g_Wh[(size_t)NTOT * KTOT];    // 64 MB, [N][K]

// ---------------------------------------------------------------------------
// helpers
// ---------------------------------------------------------------------------
__device__ __forceinline__ uint32_t smem_u32(const void* p) {
    uint32_t a;
    asm("{ .reg .u64 t; cvta.to.shared.u64 t, %1; cvt.u32.u64 %0, t; }" : "=r"(a) : "l"(p));
    return a;
}
__device__ __forceinline__ void cp_async16(uint32_t dst, const void* src) {
    asm volatile("cp.async.cg.shared.global [%0], [%1], 16;" :: "r"(dst), "l"(src) : "memory");
}
#define CP_COMMIT() asm volatile("cp.async.commit_group;" ::: "memory")
#define CP_WAIT(n)  asm volatile("cp.async.wait_group %0;" :: "n"(n) : "memory")

#define LDSM4(r0, r1, r2, r3, addr)                                            \
    asm volatile("ldmatrix.sync.aligned.m8n8.x4.shared.b16 {%0,%1,%2,%3}, [%4];" \
                 : "=r"(r0), "=r"(r1), "=r"(r2), "=r"(r3) : "r"(addr))

#define MMA_F16(d, a, b)                                                       \
    asm volatile("mma.sync.aligned.m16n8k16.row.col.f32.f16.f16.f32 "          \
                 "{%0,%1,%2,%3}, {%4,%5,%6,%7}, {%8,%9}, {%0,%1,%2,%3};"       \
                 : "+f"((d)[0]), "+f"((d)[1]), "+f"((d)[2]), "+f"((d)[3])       \
                 : "r"((a)[0]), "r"((a)[1]), "r"((a)[2]), "r"((a)[3]),          \
                   "r"((b)[0]), "r"((b)[1]))

__device__ __forceinline__ uint32_t h2bits(__half2 h) {
    return *reinterpret_cast<uint32_t*>(&h);
}

// ---------------------------------------------------------------------------
// merged prep kernel (unchanged from R13)
// ---------------------------------------------------------------------------
#define PREP_A_BLOCKS 8192
#define PREP_W_BLOCKS 8192

__global__ void prep_all(const float* __restrict__ lh, const float* __restrict__ rh,
                         const float* __restrict__ Wl, const float* __restrict__ Wr) {
    __shared__ float s[64][65];
    const int t = threadIdx.x;

    if (blockIdx.x < PREP_A_BLOCKS) {
        size_t idx = (size_t)blockIdx.x * 256 + t;
        size_t m = idx >> 9;
        int q = (int)(idx & 511);
        const float* src = (q < 256) ? (lh + (size_t)m * DDIM + q * 8)
                                     : (rh + (size_t)m * DDIM + (q - 256) * 8);
        float4 v0 = *reinterpret_cast<const float4*>(src);
        float4 v1 = *reinterpret_cast<const float4*>(src + 4);
        uint4 w;
        w.x = h2bits(__floats2half2_rn(v0.x, v0.y));
        w.y = h2bits(__floats2half2_rn(v0.z, v0.w));
        w.z = h2bits(__floats2half2_rn(v1.x, v1.y));
        w.w = h2bits(__floats2half2_rn(v1.z, v1.w));
        *reinterpret_cast<uint4*>(g_Ah + m * KTOT + ((size_t)q << 3)) = w;
        return;
    }

    const int bid = blockIdx.x - PREP_A_BLOCKS;
    const int kb = (bid & 63) * 64;
    const int nb = (bid >> 6) * 64;

    const int rr = t >> 4;
    const int c4 = (t & 15) * 4;
#pragma unroll
    for (int i = 0; i < 4; ++i) {
        int k = kb + rr + i * 16;
        const float* src = (k < DDIM) ? (Wl + (size_t)k * NTOT)
                                      : (Wr + (size_t)(k - DDIM) * NTOT);
        float4 v = *reinterpret_cast<const float4*>(src + nb + c4);
        s[rr + i * 16][c4 + 0] = v.x;
        s[rr + i * 16][c4 + 1] = v.y;
        s[rr + i * 16][c4 + 2] = v.z;
        s[rr + i * 16][c4 + 3] = v.w;
    }
    __syncthreads();

    const int koff = (t & 7) * 8;
#pragma unroll
    for (int i = 0; i < 2; ++i) {
        int nrow = (t >> 3) + i * 32;
        uint4 w;
        w.x = h2bits(__floats2half2_rn(s[koff + 0][nrow], s[koff + 1][nrow]));
        w.y = h2bits(__floats2half2_rn(s[koff + 2][nrow], s[koff + 3][nrow]));
        w.z = h2bits(__floats2half2_rn(s[koff + 4][nrow], s[koff + 5][nrow]));
        w.w = h2bits(__floats2half2_rn(s[koff + 6][nrow], s[koff + 7][nrow]));
        *reinterpret_cast<uint4*>(g_Wh + (size_t)(nb + nrow) * KTOT + kb + koff) = w;
    }
}

// ---------------------------------------------------------------------------
// Fused GEMM + gates. CTA 128m x 128n (4 gate quarters x 32 cols of D),
// BK=64 f16 (128B rows), 256 thr (8 warps 2x4, warp tile 64x32), STG=3,
// 2 CTA/SM. Mainloop identical to R13 champion.
// ---------------------------------------------------------------------------
#define BM 128
#define BN 128
#define BK 64
#define STG 3
#define KSTEPS (KTOT / BK)                 // 64
#define A_BYTES (BM * BK * 2)              // 16384
#define B_BYTES (BN * BK * 2)              // 16384
#define STAGE_BYTES (A_BYTES + B_BYTES)    // 32768
#define SMEM_BYTES (STG * STAGE_BYTES)     // 98304 (>= 128*132*4 epilogue)

__device__ __forceinline__ void load_stage_A(uint32_t as, int tid, const __half* aSrc) {
#pragma unroll
    for (int i = 0; i < 4; ++i) {
        int id = tid + (i << 8);
        int row = id >> 3, c = id & 7;
        uint32_t dst = as + row * 128 + ((c ^ (row & 7)) << 4);
        cp_async16(dst, aSrc + (size_t)row * KTOT + (c << 3));
    }
}
__device__ __forceinline__ void load_stage_B(uint32_t bs, int tid, const __half* bSrc) {
#pragma unroll
    for (int i = 0; i < 4; ++i) {
        int id = tid + (i << 8);
        int row = id >> 3, c = id & 7;
        int wrow = row + ((row >> 5) * (DDIM - 32));   // quarter gather
        uint32_t dst = bs + row * 128 + ((c ^ (row & 7)) << 4);
        cp_async16(dst, bSrc + (size_t)wrow * KTOT + (c << 3));
    }
}

// one kq group (k16): B then A fragments, then 16 MMAs (warp 64x32)
__device__ __forceinline__ void kq_group(int kq, uint32_t aWarp, uint32_t bWarp,
                                         uint32_t aco, uint32_t bco, uint32_t rr,
                                         float (&ac)[4][4][4]) {
    uint32_t b[4][2];
    uint32_t bxor = ((2 * kq + bco) ^ rr) << 4;
#pragma unroll
    for (int pi = 0; pi < 2; ++pi) {
        uint32_t r0, r1, r2, r3;
        LDSM4(r0, r1, r2, r3, bWarp + pi * 2048 + bxor);
        b[2 * pi][0] = r0; b[2 * pi][1] = r1;
        b[2 * pi + 1][0] = r2; b[2 * pi + 1][1] = r3;
    }
    uint32_t a[4][4];
    uint32_t axor = ((2 * kq + aco) ^ rr) << 4;
#pragma unroll
    for (int mi = 0; mi < 4; ++mi)
        LDSM4(a[mi][0], a[mi][1], a[mi][2], a[mi][3], aWarp + mi * 2048 + axor);
#pragma unroll
    for (int mi = 0; mi < 4; ++mi)
#pragma unroll
        for (int ni = 0; ni < 4; ++ni)
            MMA_F16(ac[mi][ni], a[mi], b[ni]);
}

__device__ __forceinline__ float sigm(float x) { return 1.0f / (1.0f + __expf(-x)); }
__device__ __forceinline__ float tanh_fast(float x) {
    return 1.0f - __fdividef(2.0f, __expf(2.0f * x) + 1.0f);
}

__global__ void __launch_bounds__(256, 2)
gemm_gates_kernel(const float* __restrict__ lc, const float* __restrict__ rc,
                  const float* __restrict__ bl, const float* __restrict__ br,
                  float* __restrict__ out) {
    extern __shared__ float smem[];
    uint32_t sbase = smem_u32(smem);
    const int tid = threadIdx.x;
    const int lane = tid & 31;
    const int wid = tid >> 5;
    const int wm = wid & 1;          // 0..1: 64-row m slice
    const int wn = wid >> 1;         // 0..3: 32-col n slice
    const int kq0 = wid & 3, kq1 = (wid + 1) & 3, kq2 = (wid + 2) & 3,
              kq3 = (wid + 3) & 3;

    const int nb = blockIdx.x * 32;
    const int m0 = blockIdx.y * BM;

    const __half* Abase = g_Ah + (size_t)m0 * KTOT;
    const __half* WtBase = g_Wh + (size_t)nb * KTOT;

    const uint32_t j = lane >> 3, rr = lane & 7;
    const uint32_t a_row_off = ((j & 1) << 3) + rr;  const uint32_t aco = j >> 1;
    const uint32_t b_row_off = ((j >> 1) << 3) + rr; const uint32_t bco = j & 1;

    uint32_t aW[STG], bW[STG];
#pragma unroll
    for (int s = 0; s < STG; ++s) {
        aW[s] = sbase + s * STAGE_BYTES + (wm * 64 + a_row_off) * 128;
        bW[s] = sbase + s * STAGE_BYTES + A_BYTES + (wn * 32 + b_row_off) * 128;
    }

    float ac[4][4][4];
#pragma unroll
    for (int mi = 0; mi < 4; ++mi)
#pragma unroll
        for (int ni = 0; ni < 4; ++ni)
#pragma unroll
            for (int q = 0; q < 4; ++q) ac[mi][ni][q] = 0.0f;

#pragma unroll
    for (int s = 0; s < STG - 1; ++s) {
        uint32_t as = sbase + s * STAGE_BYTES;
        load_stage_A(as, tid, Abase + s * BK);
        load_stage_B(as + A_BYTES, tid, WtBase + s * BK);
        CP_COMMIT();
    }

    int buf = 0;
#pragma unroll 1
    for (int ks = 0; ks < KSTEPS; ++ks) {
        CP_WAIT(1);
        __syncthreads();
        const int nxt = ks + STG - 1;
        int nbuf = buf + (STG - 1); if (nbuf >= STG) nbuf -= STG;
        const uint32_t nas = sbase + nbuf * STAGE_BYTES;
        const bool doLoad = (nxt < KSTEPS);

        kq_group(kq0, aW[buf], bW[buf], aco, bco, rr, ac);
        if (doLoad) load_stage_A(nas, tid, Abase + nxt * BK);
        kq_group(kq1, aW[buf], bW[buf], aco, bco, rr, ac);
        if (doLoad) load_stage_B(nas + A_BYTES, tid, WtBase + nxt * BK);
        kq_group(kq2, aW[buf], bW[buf], aco, bco, rr, ac);
        kq_group(kq3, aW[buf], bW[buf], aco, bco, rr, ac);
        CP_COMMIT();

        if (++buf == STG) buf = 0;
    }

    // ---- fused epilogue (float4-vectorized) ----
    CP_WAIT(0);
    __syncthreads();
    float* sG = smem;                // [128][132] padded (132 = 33 float4)
    const int gq = lane >> 2, t4 = lane & 3;
#pragma unroll
    for (int mi = 0; mi < 4; ++mi) {
#pragma unroll
        for (int ni = 0; ni < 4; ++ni) {
            int m = wm * 64 + mi * 16 + gq;
            int n = wn * 32 + ni * 8 + 2 * t4;
            sG[m * 132 + n]           = ac[mi][ni][0];
            sG[m * 132 + n + 1]       = ac[mi][ni][1];
            sG[(m + 8) * 132 + n]     = ac[mi][ni][2];
            sG[(m + 8) * 132 + n + 1] = ac[mi][ni][3];
        }
    }
    __syncthreads();

    // thread -> 4-column strip: cq = tid&7, rows tid>>3 + 32*it
    const int cq = tid & 7;
    const int r0base = tid >> 3;     // 0..31
    const int gn4 = nb + cq * 4;

    const float4 bi0 = *reinterpret_cast<const float4*>(bl + gn4);
    const float4 bi1 = *reinterpret_cast<const float4*>(br + gn4);
    const float4 bf0 = *reinterpret_cast<const float4*>(bl + DDIM + gn4);
    const float4 bf1 = *reinterpret_cast<const float4*>(br + DDIM + gn4);
    const float4 bg0 = *reinterpret_cast<const float4*>(bl + 2 * DDIM + gn4);
    const float4 bg1 = *reinterpret_cast<const float4*>(br + 2 * DDIM + gn4);
    const float4 bu0 = *reinterpret_cast<const float4*>(bl + 3 * DDIM + gn4);
    const float4 bu1 = *reinterpret_cast<const float4*>(br + 3 * DDIM + gn4);

#pragma unroll
    for (int it = 0; it < 4; ++it) {
        const int r = r0base + it * 32;
        const size_t mrow = (size_t)(m0 + r) * DDIM;
        float4 gi = *reinterpret_cast<const float4*>(sG + r * 132 + cq * 4);
        float4 gl = *reinterpret_cast<const float4*>(sG + r * 132 + 32 + cq * 4);
        float4 gr = *reinterpret_cast<const float4*>(sG + r * 132 + 64 + cq * 4);
        float4 gu = *reinterpret_cast<const float4*>(sG + r * 132 + 96 + cq * 4);
        float4 vlc = *reinterpret_cast<const float4*>(lc + mrow + gn4);
        float4 vrc = *reinterpret_cast<const float4*>(rc + mrow + gn4);
        float4 c, h;
#define GATE1(X)                                                               \
        do {                                                                   \
            float i_ = sigm(gi.X + bi0.X + bi1.X);                             \
            float lf = sigm(gl.X + bf0.X + bf1.X);                             \
            float rf = sigm(gr.X + bg0.X + bg1.X);                             \
            float u_ = tanh_fast(gu.X + bu0.X + bu1.X);                        \
            c.X = i_ * u_ + lf * vlc.X + rf * vrc.X;                           \
            h.X = tanh_fast(c.X);                                              \
        } while (0)
        GATE1(x); GATE1(y); GATE1(z); GATE1(w);
#undef GATE1
        *reinterpret_cast<float4*>(out + mrow + gn4) = c;
        *reinterpret_cast<float4*>(out + (size_t)BATCH * DDIM + mrow + gn4) = h;
    }
}

// ---------------------------------------------------------------------------
// launch — inputs: lc, lh, rc, rh, Wl, bl, Wr, br (all f32)
// ---------------------------------------------------------------------------
extern "C" void kernel_launch(void* const* d_in, const int* in_sizes, int n_in,
                              void* d_out, int out_size) {
    const float* lc = (const float*)d_in[0];
    const float* lh = (const float*)d_in[1];
    const float* rc = (const float*)d_in[2];
    const float* rh = (const float*)d_in[3];
    const float* Wl = (const float*)d_in[4];
    const float* bl = (const float*)d_in[5];
    const float* Wr = (const float*)d_in[6];
    const float* br = (const float*)d_in[7];
    float* out = (float*)d_out;

    prep_all<<<PREP_A_BLOCKS + PREP_W_BLOCKS, 256>>>(lh, rh, Wl, Wr);

    cudaFuncSetAttribute(gemm_gates_kernel,
                         cudaFuncAttributeMaxDynamicSharedMemorySize, SMEM_BYTES);
    gemm_gates_kernel<<<dim3(DDIM / 32, BATCH / BM), 256, SMEM_BYTES>>>(
        lc, rc, bl, br, out);
}